// round 2
// baseline (speedup 1.0000x reference)
#include <cuda_runtime.h>
#include <math.h>

// Problem constants
#define PV 32000   // vocab
#define PKC 3      // k-gram
#define PD 1024    // embed dim
#define PS 2048    // seq len
#define PB 2       // batch
#define PM (PS*PB)       // 4096 rows
#define PK1 (PKC*PD)     // 3072

// Scratch (device globals — allowed; no runtime allocation)
__device__ float g_X[(size_t)PM * PK1];   // gathered context embeddings (4096 x 3072)
__device__ float g_H[(size_t)PM * PD];    // hidden after silu (4096 x 1024)
__device__ int   g_tok64;                 // 1 if tokens buffer is int64, 0 if int32

// ---------------------------------------------------------------------------
// Kernel 0: detect token dtype. JAX without x64 silently downcasts the
// reference's int64 tokens to int32. Interpreting the buffer as int64 pairs:
// if all high 32-bit words of the first 32 slots are zero, it's real int64.
// ---------------------------------------------------------------------------
__global__ void detect_tok_dtype(const unsigned int* __restrict__ t) {
    int is64 = 1;
    #pragma unroll
    for (int i = 0; i < 32; i++)
        if (t[2 * i + 1] != 0u) { is64 = 0; break; }
    g_tok64 = is64;
}

// ---------------------------------------------------------------------------
// Kernel 1: gather context embeddings.
// X[m, j*D + d] = embedding[ tok(t-K+j, b) ][d], padded with token id 0.
// grid = (M, K), block = 256 (each thread copies one float4 of the D=1024 row)
// ---------------------------------------------------------------------------
__global__ void gather_ctx(const void* __restrict__ tokens,
                           const float* __restrict__ emb) {
    int m = blockIdx.x;
    int j = blockIdx.y;
    int t = m / PB;
    int b = m - t * PB;
    int idx = t - PKC + j;

    long long tok = 0;
    if (idx >= 0) {
        size_t ofs = (size_t)idx * PB + b;
        if (g_tok64) tok = ((const long long*)tokens)[ofs];
        else         tok = (long long)((const int*)tokens)[ofs];
    }
    // Safety clamp: wrong-dtype interpretation becomes a rel_err signal,
    // not an illegal access.
    if (tok < 0) tok = 0;
    if (tok >= PV) tok = PV - 1;

    const float4* src = reinterpret_cast<const float4*>(emb + (size_t)tok * PD);
    float4* dst = reinterpret_cast<float4*>(g_X + (size_t)m * PK1 + (size_t)j * PD);
    dst[threadIdx.x] = src[threadIdx.x];
}

// ---------------------------------------------------------------------------
// Classic fp32 SGEMM: C = A(MxK, row) * B(KxN, row) + bias, optional SiLU.
// 128x128 block tile, BK=16, 256 threads, 8x8 per-thread microtile.
// All dims are exact multiples of tiles for this problem — no bounds checks.
// EPI: 0 = bias + SiLU, 1 = bias only.
// ---------------------------------------------------------------------------
template<int EPI>
__global__ __launch_bounds__(256, 2) void sgemm128(
    const float* __restrict__ A, const float* __restrict__ Bm,
    const float* __restrict__ bias, float* __restrict__ C,
    int Mdim, int Ndim, int Kdim)
{
    constexpr int BM = 128, BN = 128, BK = 16;

    __shared__ float As[BK][BM];   // transposed A tile
    __shared__ float Bs[BK][BN];

    const int tid = threadIdx.x;
    const int tx = tid & 15;       // 0..15  (column group: 8 cols each)
    const int ty = tid >> 4;       // 0..15  (row group: 8 rows each)
    const int row0 = blockIdx.y * BM;
    const int col0 = blockIdx.x * BN;

    float acc[8][8];
    #pragma unroll
    for (int i = 0; i < 8; i++)
        #pragma unroll
        for (int j = 0; j < 8; j++)
            acc[i][j] = 0.0f;

    for (int k0 = 0; k0 < Kdim; k0 += BK) {
        // Load A tile 128x16, store transposed: As[k][m]
        #pragma unroll
        for (int i = tid; i < BM * BK / 4; i += 256) {
            int row = i >> 2;        // 0..127
            int c4  = i & 3;         // 0..3  (float4 within the 16-wide row)
            float4 f = *reinterpret_cast<const float4*>(
                A + (size_t)(row0 + row) * Kdim + k0 + c4 * 4);
            As[c4 * 4 + 0][row] = f.x;
            As[c4 * 4 + 1][row] = f.y;
            As[c4 * 4 + 2][row] = f.z;
            As[c4 * 4 + 3][row] = f.w;
        }
        // Load B tile 16x128 directly
        #pragma unroll
        for (int i = tid; i < BK * BN / 4; i += 256) {
            int row = i >> 5;        // 0..15
            int c4  = i & 31;        // 0..31
            *reinterpret_cast<float4*>(&Bs[row][c4 * 4]) =
                *reinterpret_cast<const float4*>(
                    Bm + (size_t)(k0 + row) * Ndim + col0 + c4 * 4);
        }
        __syncthreads();

        #pragma unroll
        for (int k = 0; k < BK; k++) {
            float ra[8], rb[8];
            float4 a0 = *reinterpret_cast<const float4*>(&As[k][ty * 8 + 0]);
            float4 a1 = *reinterpret_cast<const float4*>(&As[k][ty * 8 + 4]);
            float4 b0 = *reinterpret_cast<const float4*>(&Bs[k][tx * 8 + 0]);
            float4 b1 = *reinterpret_cast<const float4*>(&Bs[k][tx * 8 + 4]);
            ra[0]=a0.x; ra[1]=a0.y; ra[2]=a0.z; ra[3]=a0.w;
            ra[4]=a1.x; ra[5]=a1.y; ra[6]=a1.z; ra[7]=a1.w;
            rb[0]=b0.x; rb[1]=b0.y; rb[2]=b0.z; rb[3]=b0.w;
            rb[4]=b1.x; rb[5]=b1.y; rb[6]=b1.z; rb[7]=b1.w;
            #pragma unroll
            for (int i = 0; i < 8; i++)
                #pragma unroll
                for (int j = 0; j < 8; j++)
                    acc[i][j] += ra[i] * rb[j];
        }
        __syncthreads();
    }

    // Epilogue: bias (+ SiLU), vectorized stores
    float bb[8];
    #pragma unroll
    for (int j = 0; j < 8; j++)
        bb[j] = bias[col0 + tx * 8 + j];

    #pragma unroll
    for (int i = 0; i < 8; i++) {
        size_t r = (size_t)(row0 + ty * 8 + i);
        float v[8];
        #pragma unroll
        for (int j = 0; j < 8; j++) {
            float x = acc[i][j] + bb[j];
            if (EPI == 0) x = x / (1.0f + expf(-x));   // silu
            v[j] = x;
        }
        float* cp = C + r * Ndim + col0 + tx * 8;
        *reinterpret_cast<float4*>(cp + 0) = make_float4(v[0], v[1], v[2], v[3]);
        *reinterpret_cast<float4*>(cp + 4) = make_float4(v[4], v[5], v[6], v[7]);
    }
}

// ---------------------------------------------------------------------------
extern "C" void kernel_launch(void* const* d_in, const int* in_sizes, int n_in,
                              void* d_out, int out_size) {
    const void*  tokens = d_in[0];                        // (S,B) int64 OR int32
    const float* emb = (const float*)d_in[1];             // (V,D)
    const float* W1  = (const float*)d_in[2];             // (K*D, D)
    const float* b1  = (const float*)d_in[3];             // (D,)
    const float* W2  = (const float*)d_in[4];             // (D, V)
    const float* b2  = (const float*)d_in[5];             // (V,)
    float* out = (float*)d_out;                           // (S,B,V) fp32

    float *pX = nullptr, *pH = nullptr;
    cudaGetSymbolAddress((void**)&pX, g_X);
    cudaGetSymbolAddress((void**)&pH, g_H);

    // 0) detect token dtype (int32 vs int64)
    detect_tok_dtype<<<1, 1>>>((const unsigned int*)tokens);

    // 1) gather context embeddings -> X (4096 x 3072)
    gather_ctx<<<dim3(PM, PKC), 256>>>(tokens, emb);

    // 2) H = silu(X @ W1 + b1)   : 4096 x 1024 x 3072
    sgemm128<0><<<dim3(PD / 128, PM / 128), 256>>>(pX, W1, b1, pH, PM, PD, PK1);

    // 3) out = H @ W2 + b2       : 4096 x 32000 x 1024
    sgemm128<1><<<dim3(PV / 128, PM / 128), 256>>>(pH, W2, b2, out, PM, PV, PD);
}

// round 4
// speedup vs baseline: 2.8043x; 2.8043x over previous
#include <cuda_runtime.h>
#include <cuda_bf16.h>
#include <math.h>
#include <stdint.h>

// Problem constants
#define PV 32000
#define PKC 3
#define PD 1024
#define PS 2048
#define PB 2
#define PM (PS*PB)      // 4096
#define PK1 (PKC*PD)    // 3072

// ---------------------------------------------------------------------------
// Scratch (device globals — allocation-guard-safe). All values tf32-rounded.
// ---------------------------------------------------------------------------
__device__ float g_X[(size_t)PM * PK1];    // gathered ctx (4096 x 3072)
__device__ float g_H[(size_t)PM * PD];     // hidden (4096 x 1024)
__device__ float g_W1t[(size_t)PD * PK1];  // W1^T  [N=1024][K=3072]
__device__ float g_W2t[(size_t)PV * PD];   // W2^T  [N=32000][K=1024]
__device__ int g_tok64;

// ---------------------------------------------------------------------------
// helpers
// ---------------------------------------------------------------------------
__device__ __forceinline__ float tf32r(float x) {
    uint32_t u;
    asm("cvt.rna.tf32.f32 %0, %1;" : "=r"(u) : "f"(x));
    return __uint_as_float(u);
}
__device__ __forceinline__ uint32_t smem_u32(const void* p) {
    uint32_t a;
    asm("{ .reg .u64 t; cvta.to.shared.u64 t, %1; cvt.u32.u64 %0, t; }" : "=r"(a) : "l"(p));
    return a;
}
__device__ __forceinline__ void cp_async16(uint32_t dst, const void* src) {
    asm volatile("cp.async.cg.shared.global [%0], [%1], 16;" :: "r"(dst), "l"(src));
}
__device__ __forceinline__ void cp_commit() { asm volatile("cp.async.commit_group;" ::: "memory"); }
template<int N> __device__ __forceinline__ void cp_wait() {
    asm volatile("cp.async.wait_group %0;" :: "n"(N) : "memory");
}
// m16n8k8 tf32 MMA, fp32 accum
__device__ __forceinline__ void mma_tf32(float* c, const uint32_t* a, const uint32_t* b) {
    asm volatile(
        "mma.sync.aligned.m16n8k8.row.col.f32.tf32.tf32.f32 "
        "{%0,%1,%2,%3}, {%4,%5,%6,%7}, {%8,%9}, {%0,%1,%2,%3};"
        : "+f"(c[0]), "+f"(c[1]), "+f"(c[2]), "+f"(c[3])
        : "r"(a[0]), "r"(a[1]), "r"(a[2]), "r"(a[3]), "r"(b[0]), "r"(b[1]));
}

// ---------------------------------------------------------------------------
// Kernel 0: token dtype detection (JAX may downcast int64 -> int32)
// ---------------------------------------------------------------------------
__global__ void detect_tok_dtype(const unsigned int* __restrict__ t) {
    int is64 = 1;
    #pragma unroll
    for (int i = 0; i < 32; i++)
        if (t[2 * i + 1] != 0u) { is64 = 0; break; }
    g_tok64 = is64;
}

// ---------------------------------------------------------------------------
// Kernel 1: gather context embeddings -> tf32-rounded X. grid (PM,PKC), 256thr
// ---------------------------------------------------------------------------
__global__ void gather_ctx(const void* __restrict__ tokens, const float* __restrict__ emb) {
    int m = blockIdx.x, j = blockIdx.y;
    int t = m / PB, b = m - t * PB;
    int idx = t - PKC + j;
    long long tok = 0;
    if (idx >= 0) {
        size_t ofs = (size_t)idx * PB + b;
        tok = g_tok64 ? ((const long long*)tokens)[ofs]
                      : (long long)((const int*)tokens)[ofs];
    }
    if (tok < 0) tok = 0;
    if (tok >= PV) tok = PV - 1;
    float4 f = reinterpret_cast<const float4*>(emb + (size_t)tok * PD)[threadIdx.x];
    f.x = tf32r(f.x); f.y = tf32r(f.y); f.z = tf32r(f.z); f.w = tf32r(f.w);
    *reinterpret_cast<float4*>(g_X + (size_t)m * PK1 + (size_t)j * PD
                               + (size_t)threadIdx.x * 4) = f;
}

// ---------------------------------------------------------------------------
// Kernel 2: W [Kdim][Ndim] fp32 -> transposed tf32-rounded [Ndim][Kdim]
// ---------------------------------------------------------------------------
__global__ void transpose_tf32(const float* __restrict__ W, float* __restrict__ Bt,
                               int Kdim, int Ndim) {
    __shared__ float tile[32][33];
    int n0 = blockIdx.x * 32, k0 = blockIdx.y * 32;
    int tx = threadIdx.x, ty = threadIdx.y;
    tile[ty][tx] = W[(size_t)(k0 + ty) * Ndim + n0 + tx];
    __syncthreads();
    Bt[(size_t)(n0 + ty) * Kdim + k0 + tx] = tf32r(tile[tx][ty]);
}

// ---------------------------------------------------------------------------
// tf32 mma.sync GEMM: C = A(MxK) @ B(NxK)^T + bias (EPI0: silu+tf32 round)
// CTA tile 128x128, BK=32, 3-stage cp.async pipeline, 8 warps (2M x 4N),
// warp tile 64x32 (4x4 mma of m16n8k8).
// ---------------------------------------------------------------------------
#define BMT 128
#define BNT 128
#define BKT 32
#define NSTG 3
#define APAD 36                          // floats per smem row (32+4)
#define A_STG (BMT*APAD)                 // floats
#define B_STG (BNT*APAD)
#define STG_FLT (A_STG + B_STG)
#define SMEM_BYTES (NSTG * STG_FLT * 4)  // 110592

template<int EPI>
__device__ __forceinline__ void issue_stage(
    uint32_t sm_base, int s, const float* __restrict__ A, const float* __restrict__ B,
    int row0, int col0, int k0, int Kdim, int tid)
{
    uint32_t st = sm_base + (uint32_t)(s * STG_FLT) * 4u;
    #pragma unroll
    for (int j = 0; j < 4; j++) {
        int i = tid + j * 256;           // A: 1024 16B-chunks
        int row = i >> 3, c = i & 7;
        cp_async16(st + (uint32_t)(row * APAD + c * 4) * 4u,
                   A + (size_t)(row0 + row) * Kdim + k0 + c * 4);
    }
    uint32_t stb = st + (uint32_t)A_STG * 4u;
    #pragma unroll
    for (int j = 0; j < 4; j++) {
        int i = tid + j * 256;           // B: 1024 16B-chunks
        int row = i >> 3, c = i & 7;
        cp_async16(stb + (uint32_t)(row * APAD + c * 4) * 4u,
                   B + (size_t)(col0 + row) * Kdim + k0 + c * 4);
    }
}

template<int EPI>
__global__ __launch_bounds__(256, 1)
void mma_gemm(const float* __restrict__ A, const float* __restrict__ B,
              const float* __restrict__ bias, float* __restrict__ C,
              int Ndim, int Kdim)
{
    extern __shared__ float smf[];
    const uint32_t sm_base = smem_u32(smf);

    const int tid = threadIdx.x;
    const int wid = tid >> 5, lane = tid & 31;
    const int wm = wid >> 2;             // 0..1  -> M offset wm*64
    const int wn = wid & 3;              // 0..3  -> N offset wn*32
    const int gq = lane >> 2;            // groupID 0..7
    const int tg = lane & 3;             // threadInGroup 0..3

    const int row0 = blockIdx.x * BMT;
    const int col0 = blockIdx.y * BNT;
    const int NC = Kdim / BKT;

    float acc[4][4][4];
    #pragma unroll
    for (int mi = 0; mi < 4; mi++)
        #pragma unroll
        for (int ni = 0; ni < 4; ni++)
            #pragma unroll
            for (int q = 0; q < 4; q++) acc[mi][ni][q] = 0.0f;

    // prologue: stages 0..NSTG-2
    #pragma unroll
    for (int s = 0; s < NSTG - 1; s++) {
        issue_stage<EPI>(sm_base, s, A, B, row0, col0, s * BKT, Kdim, tid);
        cp_commit();
    }

    for (int c = 0; c < NC; c++) {
        int nc = c + NSTG - 1;
        if (nc < NC)
            issue_stage<EPI>(sm_base, nc % NSTG, A, B, row0, col0, nc * BKT, Kdim, tid);
        cp_commit();
        cp_wait<NSTG - 1>();
        __syncthreads();

        const float* As = smf + (c % NSTG) * STG_FLT;
        const float* Bs = As + A_STG;

        #pragma unroll
        for (int kk = 0; kk < 4; kk++) {
            const int k = kk * 8;
            uint32_t af[4][4], bf[4][2];
            #pragma unroll
            for (int mi = 0; mi < 4; mi++) {
                int m0 = wm * 64 + mi * 16 + gq;
                af[mi][0] = __float_as_uint(As[(m0    ) * APAD + k + tg    ]);
                af[mi][1] = __float_as_uint(As[(m0 + 8) * APAD + k + tg    ]);
                af[mi][2] = __float_as_uint(As[(m0    ) * APAD + k + tg + 4]);
                af[mi][3] = __float_as_uint(As[(m0 + 8) * APAD + k + tg + 4]);
            }
            #pragma unroll
            for (int ni = 0; ni < 4; ni++) {
                int n0 = wn * 32 + ni * 8 + gq;
                bf[ni][0] = __float_as_uint(Bs[n0 * APAD + k + tg    ]);
                bf[ni][1] = __float_as_uint(Bs[n0 * APAD + k + tg + 4]);
            }
            #pragma unroll
            for (int mi = 0; mi < 4; mi++)
                #pragma unroll
                for (int ni = 0; ni < 4; ni++)
                    mma_tf32(acc[mi][ni], af[mi], bf[ni]);
        }
        __syncthreads();
    }

    // Epilogue
    #pragma unroll
    for (int mi = 0; mi < 4; mi++) {
        const int r0 = row0 + wm * 64 + mi * 16 + gq;
        #pragma unroll
        for (int ni = 0; ni < 4; ni++) {
            const int cl = col0 + wn * 32 + ni * 8 + 2 * tg;
            float bb0 = bias[cl], bb1 = bias[cl + 1];
            float v0 = acc[mi][ni][0] + bb0, v1 = acc[mi][ni][1] + bb1;
            float v2 = acc[mi][ni][2] + bb0, v3 = acc[mi][ni][3] + bb1;
            if (EPI == 0) {
                v0 = tf32r(v0 / (1.0f + expf(-v0)));
                v1 = tf32r(v1 / (1.0f + expf(-v1)));
                v2 = tf32r(v2 / (1.0f + expf(-v2)));
                v3 = tf32r(v3 / (1.0f + expf(-v3)));
            }
            *reinterpret_cast<float2*>(C + (size_t)r0 * Ndim + cl) = make_float2(v0, v1);
            *reinterpret_cast<float2*>(C + (size_t)(r0 + 8) * Ndim + cl) = make_float2(v2, v3);
        }
    }
}

// ---------------------------------------------------------------------------
extern "C" void kernel_launch(void* const* d_in, const int* in_sizes, int n_in,
                              void* d_out, int out_size) {
    const void*  tokens = d_in[0];
    const float* emb = (const float*)d_in[1];
    const float* W1  = (const float*)d_in[2];
    const float* b1  = (const float*)d_in[3];
    const float* W2  = (const float*)d_in[4];
    const float* b2  = (const float*)d_in[5];
    float* out = (float*)d_out;

    float *pX, *pH, *pW1t, *pW2t;
    cudaGetSymbolAddress((void**)&pX, g_X);
    cudaGetSymbolAddress((void**)&pH, g_H);
    cudaGetSymbolAddress((void**)&pW1t, g_W1t);
    cudaGetSymbolAddress((void**)&pW2t, g_W2t);

    cudaFuncSetAttribute(mma_gemm<0>, cudaFuncAttributeMaxDynamicSharedMemorySize, SMEM_BYTES);
    cudaFuncSetAttribute(mma_gemm<1>, cudaFuncAttributeMaxDynamicSharedMemorySize, SMEM_BYTES);

    // 0) token dtype
    detect_tok_dtype<<<1, 1>>>((const unsigned int*)tokens);
    // 1) gather -> tf32-rounded X
    gather_ctx<<<dim3(PM, PKC), 256>>>(tokens, emb);
    // 2) transpose weights -> [N][K] tf32
    transpose_tf32<<<dim3(PD / 32, PK1 / 32), dim3(32, 32)>>>(W1, pW1t, PK1, PD);
    transpose_tf32<<<dim3(PV / 32, PD / 32), dim3(32, 32)>>>(W2, pW2t, PD, PV);
    // 3) H = silu(X @ W1^T + b1)   M=4096,N=1024,K=3072  (grid x = M for L2 reuse)
    mma_gemm<0><<<dim3(PM / BMT, PD / BNT), 256, SMEM_BYTES>>>(pX, pW1t, b1, pH, PD, PK1);
    // 4) out = H @ W2^T + b2       M=4096,N=32000,K=1024
    mma_gemm<1><<<dim3(PM / BMT, PV / BNT), 256, SMEM_BYTES>>>(pH, pW2t, b2, out, PV, PD);
}

// round 5
// speedup vs baseline: 3.4634x; 1.2350x over previous
#include <cuda_runtime.h>
#include <math.h>
#include <stdint.h>

// Problem constants
#define PV 32000
#define PKC 3
#define PD 1024
#define PS 2048
#define PB 2
#define PM (PS*PB)      // 4096
#define PK1 (PKC*PD)    // 3072

// ---------------------------------------------------------------------------
// Scratch (device globals). All tf32-rounded.
// ---------------------------------------------------------------------------
__device__ float g_X[(size_t)PM * PK1];    // gathered ctx (4096 x 3072)
__device__ float g_H[(size_t)PM * PD];     // hidden (4096 x 1024)
__device__ float g_W1r[(size_t)PK1 * PD];  // W1 rounded, [K=3072][N=1024]
__device__ float g_W2r[(size_t)PD * PV];   // W2 rounded, [K=1024][N=32000]
__device__ int g_tok64;

// ---------------------------------------------------------------------------
// helpers
// ---------------------------------------------------------------------------
__device__ __forceinline__ float tf32r(float x) {
    uint32_t u;
    asm("cvt.rna.tf32.f32 %0, %1;" : "=r"(u) : "f"(x));
    return __uint_as_float(u);
}
__device__ __forceinline__ uint32_t smem_u32(const void* p) {
    uint32_t a;
    asm("{ .reg .u64 t; cvta.to.shared.u64 t, %1; cvt.u32.u64 %0, t; }" : "=r"(a) : "l"(p));
    return a;
}
__device__ __forceinline__ void cp_async16(uint32_t dst, const void* src) {
    asm volatile("cp.async.cg.shared.global [%0], [%1], 16;" :: "r"(dst), "l"(src));
}
__device__ __forceinline__ void cp_commit() { asm volatile("cp.async.commit_group;" ::: "memory"); }
template<int N> __device__ __forceinline__ void cp_wait() {
    asm volatile("cp.async.wait_group %0;" :: "n"(N) : "memory");
}
__device__ __forceinline__ void mma_tf32(float* c, const uint32_t* a, const uint32_t* b) {
    asm volatile(
        "mma.sync.aligned.m16n8k8.row.col.f32.tf32.tf32.f32 "
        "{%0,%1,%2,%3}, {%4,%5,%6,%7}, {%8,%9}, {%0,%1,%2,%3};"
        : "+f"(c[0]), "+f"(c[1]), "+f"(c[2]), "+f"(c[3])
        : "r"(a[0]), "r"(a[1]), "r"(a[2]), "r"(a[3]), "r"(b[0]), "r"(b[1]));
}

// ---------------------------------------------------------------------------
// Kernel 0: token dtype detection (JAX may downcast int64 -> int32)
// ---------------------------------------------------------------------------
__global__ void detect_tok_dtype(const unsigned int* __restrict__ t) {
    int is64 = 1;
    #pragma unroll
    for (int i = 0; i < 32; i++)
        if (t[2 * i + 1] != 0u) { is64 = 0; break; }
    g_tok64 = is64;
}

// ---------------------------------------------------------------------------
// Kernel 1: gather context embeddings -> tf32-rounded X. grid (PM,PKC), 256thr
// ---------------------------------------------------------------------------
__global__ void gather_ctx(const void* __restrict__ tokens, const float* __restrict__ emb) {
    int m = blockIdx.x, j = blockIdx.y;
    int t = m / PB, b = m - t * PB;
    int idx = t - PKC + j;
    long long tok = 0;
    if (idx >= 0) {
        size_t ofs = (size_t)idx * PB + b;
        tok = g_tok64 ? ((const long long*)tokens)[ofs]
                      : (long long)((const int*)tokens)[ofs];
    }
    if (tok < 0) tok = 0;
    if (tok >= PV) tok = PV - 1;
    float4 f = reinterpret_cast<const float4*>(emb + (size_t)tok * PD)[threadIdx.x];
    f.x = tf32r(f.x); f.y = tf32r(f.y); f.z = tf32r(f.z); f.w = tf32r(f.w);
    *reinterpret_cast<float4*>(g_X + (size_t)m * PK1 + (size_t)j * PD
                               + (size_t)threadIdx.x * 4) = f;
}

// ---------------------------------------------------------------------------
// Kernel 2: streaming tf32 round-copy (keeps [K][N] layout — no transpose)
// ---------------------------------------------------------------------------
__global__ void round_copy(const float* __restrict__ src, float* __restrict__ dst, size_t n4) {
    size_t i = (size_t)blockIdx.x * blockDim.x + threadIdx.x;
    if (i >= n4) return;
    float4 f = reinterpret_cast<const float4*>(src)[i];
    f.x = tf32r(f.x); f.y = tf32r(f.y); f.z = tf32r(f.z); f.w = tf32r(f.w);
    reinterpret_cast<float4*>(dst)[i] = f;
}

// ---------------------------------------------------------------------------
// tf32 mma.sync GEMM: C = A(MxK,row) @ B(KxN,row) + bias (EPI0: silu+tf32)
// CTA tile 128x256, BK=32, 3-stage cp.async pipeline, 8 warps (2M x 4N),
// warp tile 64x64 (4x8 mma of m16n8k8 per k8-step).
// A smem [128][36] m-major; B smem [32][264] k-major.
// ---------------------------------------------------------------------------
#define BMT 128
#define BNT 256
#define BKT 32
#define NSTG 3
#define APAD 36
#define BPAD 264
#define A_STG (BMT*APAD)            // 4608 floats
#define B_STG (BKT*BPAD)            // 8448 floats
#define STG_FLT (A_STG + B_STG)     // 13056
#define SMEM_BYTES (NSTG * STG_FLT * 4)   // 156672

__device__ __forceinline__ void issue_stage(
    uint32_t sm_base, int s, const float* __restrict__ A, const float* __restrict__ Bm,
    int row0, int col0, int k0, int Kdim, int Ndim, int tid)
{
    uint32_t st = sm_base + (uint32_t)(s * STG_FLT) * 4u;
    // A: 128 rows x 32 floats = 1024 16B chunks
    #pragma unroll
    for (int j = 0; j < 4; j++) {
        int i = tid + j * 256;
        int row = i >> 3, c = i & 7;
        cp_async16(st + (uint32_t)(row * APAD + c * 4) * 4u,
                   A + (size_t)(row0 + row) * Kdim + k0 + c * 4);
    }
    // B: 32 k-rows x 256 floats = 2048 16B chunks
    uint32_t stb = st + (uint32_t)A_STG * 4u;
    #pragma unroll
    for (int j = 0; j < 8; j++) {
        int i = tid + j * 256;
        int row = i >> 6, c = i & 63;
        cp_async16(stb + (uint32_t)(row * BPAD + c * 4) * 4u,
                   Bm + (size_t)(k0 + row) * Ndim + col0 + c * 4);
    }
}

template<int EPI>
__global__ __launch_bounds__(256, 1)
void mma_gemm(const float* __restrict__ A, const float* __restrict__ Bm,
              const float* __restrict__ bias, float* __restrict__ C,
              int Ndim, int Kdim)
{
    extern __shared__ float smf[];
    const uint32_t sm_base = smem_u32(smf);

    const int tid = threadIdx.x;
    const int wid = tid >> 5, lane = tid & 31;
    const int wm = wid >> 2;             // 0..1  -> M offset wm*64
    const int wn = wid & 3;              // 0..3  -> N offset wn*64
    const int gq = lane >> 2;            // 0..7
    const int tg = lane & 3;             // 0..3

    const int row0 = blockIdx.x * BMT;
    const int col0 = blockIdx.y * BNT;
    const int NC = Kdim / BKT;

    float acc[4][8][4];
    #pragma unroll
    for (int mi = 0; mi < 4; mi++)
        #pragma unroll
        for (int ni = 0; ni < 8; ni++)
            #pragma unroll
            for (int q = 0; q < 4; q++) acc[mi][ni][q] = 0.0f;

    #pragma unroll
    for (int s = 0; s < NSTG - 1; s++) {
        issue_stage(sm_base, s, A, Bm, row0, col0, s * BKT, Kdim, Ndim, tid);
        cp_commit();
    }

    for (int c = 0; c < NC; c++) {
        int nc = c + NSTG - 1;
        if (nc < NC)
            issue_stage(sm_base, nc % NSTG, A, Bm, row0, col0, nc * BKT, Kdim, Ndim, tid);
        cp_commit();
        cp_wait<NSTG - 1>();
        __syncthreads();

        const float* As = smf + (c % NSTG) * STG_FLT;
        const float* Bs = As + A_STG;

        #pragma unroll
        for (int kk = 0; kk < 4; kk++) {
            const int k = kk * 8;
            uint32_t af[4][4], bf[8][2];
            #pragma unroll
            for (int mi = 0; mi < 4; mi++) {
                int m0 = wm * 64 + mi * 16 + gq;
                af[mi][0] = __float_as_uint(As[(m0    ) * APAD + k + tg    ]);
                af[mi][1] = __float_as_uint(As[(m0 + 8) * APAD + k + tg    ]);
                af[mi][2] = __float_as_uint(As[(m0    ) * APAD + k + tg + 4]);
                af[mi][3] = __float_as_uint(As[(m0 + 8) * APAD + k + tg + 4]);
            }
            #pragma unroll
            for (int ni = 0; ni < 8; ni++) {
                int n0 = wn * 64 + ni * 8 + gq;
                bf[ni][0] = __float_as_uint(Bs[(k + tg    ) * BPAD + n0]);
                bf[ni][1] = __float_as_uint(Bs[(k + tg + 4) * BPAD + n0]);
            }
            #pragma unroll
            for (int mi = 0; mi < 4; mi++)
                #pragma unroll
                for (int ni = 0; ni < 8; ni++)
                    mma_tf32(acc[mi][ni], af[mi], bf[ni]);
        }
        __syncthreads();
    }

    // Epilogue
    #pragma unroll
    for (int mi = 0; mi < 4; mi++) {
        const int r0 = row0 + wm * 64 + mi * 16 + gq;
        #pragma unroll
        for (int ni = 0; ni < 8; ni++) {
            const int cl = col0 + wn * 64 + ni * 8 + 2 * tg;
            float bb0 = bias[cl], bb1 = bias[cl + 1];
            float v0 = acc[mi][ni][0] + bb0, v1 = acc[mi][ni][1] + bb1;
            float v2 = acc[mi][ni][2] + bb0, v3 = acc[mi][ni][3] + bb1;
            if (EPI == 0) {
                v0 = tf32r(v0 / (1.0f + expf(-v0)));
                v1 = tf32r(v1 / (1.0f + expf(-v1)));
                v2 = tf32r(v2 / (1.0f + expf(-v2)));
                v3 = tf32r(v3 / (1.0f + expf(-v3)));
            }
            *reinterpret_cast<float2*>(C + (size_t)r0 * Ndim + cl) = make_float2(v0, v1);
            *reinterpret_cast<float2*>(C + (size_t)(r0 + 8) * Ndim + cl) = make_float2(v2, v3);
        }
    }
}

// ---------------------------------------------------------------------------
extern "C" void kernel_launch(void* const* d_in, const int* in_sizes, int n_in,
                              void* d_out, int out_size) {
    const void*  tokens = d_in[0];
    const float* emb = (const float*)d_in[1];
    const float* W1  = (const float*)d_in[2];
    const float* b1  = (const float*)d_in[3];
    const float* W2  = (const float*)d_in[4];
    const float* b2  = (const float*)d_in[5];
    float* out = (float*)d_out;

    float *pX, *pH, *pW1r, *pW2r;
    cudaGetSymbolAddress((void**)&pX, g_X);
    cudaGetSymbolAddress((void**)&pH, g_H);
    cudaGetSymbolAddress((void**)&pW1r, g_W1r);
    cudaGetSymbolAddress((void**)&pW2r, g_W2r);

    cudaFuncSetAttribute(mma_gemm<0>, cudaFuncAttributeMaxDynamicSharedMemorySize, SMEM_BYTES);
    cudaFuncSetAttribute(mma_gemm<1>, cudaFuncAttributeMaxDynamicSharedMemorySize, SMEM_BYTES);

    // 0) token dtype
    detect_tok_dtype<<<1, 1>>>((const unsigned int*)tokens);
    // 1) gather -> tf32-rounded X
    gather_ctx<<<dim3(PM, PKC), 256>>>(tokens, emb);
    // 2) round-copy weights (layout preserved)
    {
        size_t n4 = (size_t)PK1 * PD / 4;
        round_copy<<<(unsigned)((n4 + 255) / 256), 256>>>(W1, pW1r, n4);
        n4 = (size_t)PD * PV / 4;
        round_copy<<<(unsigned)((n4 + 255) / 256), 256>>>(W2, pW2r, n4);
    }
    // 3) H = silu(X @ W1 + b1)   M=4096,N=1024,K=3072
    mma_gemm<0><<<dim3(PM / BMT, PD / BNT), 256, SMEM_BYTES>>>(pX, pW1r, b1, pH, PD, PK1);
    // 4) out = H @ W2 + b2       M=4096,N=32000,K=1024
    mma_gemm<1><<<dim3(PM / BMT, PV / BNT), 256, SMEM_BYTES>>>(pH, pW2r, b2, out, PV, PD);
}

// round 6
// speedup vs baseline: 6.0082x; 1.7348x over previous
#include <cuda_runtime.h>
#include <cuda_fp16.h>
#include <math.h>
#include <stdint.h>

// Problem constants
#define PV 32000
#define PKC 3
#define PD 1024
#define PS 2048
#define PB 2
#define PM (PS*PB)      // 4096
#define PK1 (PKC*PD)    // 3072

// ---------------------------------------------------------------------------
// Scratch (device globals)
// ---------------------------------------------------------------------------
__device__ __half   g_X[(size_t)PM * PK1];        // gathered ctx, fp16
__device__ __half   g_H[(size_t)PM * PD];         // hidden, fp16
__device__ uint32_t g_W1p[(size_t)(PK1/2) * PD];  // W1 k-pair-packed half2 [K/2][N]
__device__ uint32_t g_W2p[(size_t)(PD/2) * PV];   // W2 k-pair-packed half2 [K/2][N]
__device__ int g_tok64;

// ---------------------------------------------------------------------------
// helpers
// ---------------------------------------------------------------------------
__device__ __forceinline__ uint32_t smem_u32(const void* p) {
    uint32_t a;
    asm("{ .reg .u64 t; cvta.to.shared.u64 t, %1; cvt.u32.u64 %0, t; }" : "=r"(a) : "l"(p));
    return a;
}
__device__ __forceinline__ void cp_async16(uint32_t dst, const void* src) {
    asm volatile("cp.async.cg.shared.global [%0], [%1], 16;" :: "r"(dst), "l"(src));
}
__device__ __forceinline__ void cp_commit() { asm volatile("cp.async.commit_group;" ::: "memory"); }
template<int N> __device__ __forceinline__ void cp_wait() {
    asm volatile("cp.async.wait_group %0;" :: "n"(N) : "memory");
}
// m16n8k16 fp16 MMA, fp32 accum
__device__ __forceinline__ void mma_f16(float* c, const uint32_t* a, const uint32_t* b) {
    asm volatile(
        "mma.sync.aligned.m16n8k16.row.col.f32.f16.f16.f32 "
        "{%0,%1,%2,%3}, {%4,%5,%6,%7}, {%8,%9}, {%0,%1,%2,%3};"
        : "+f"(c[0]), "+f"(c[1]), "+f"(c[2]), "+f"(c[3])
        : "r"(a[0]), "r"(a[1]), "r"(a[2]), "r"(a[3]), "r"(b[0]), "r"(b[1]));
}
__device__ __forceinline__ uint32_t pack2(float a, float b) {
    __half2 h = __halves2half2(__float2half(a), __float2half(b));   // low=a(k), high=b(k+1)
    return *reinterpret_cast<uint32_t*>(&h);
}

// ---------------------------------------------------------------------------
// Kernel 0: token dtype detection (JAX may downcast int64 -> int32)
// ---------------------------------------------------------------------------
__global__ void detect_tok_dtype(const unsigned int* __restrict__ t) {
    int is64 = 1;
    #pragma unroll
    for (int i = 0; i < 32; i++)
        if (t[2 * i + 1] != 0u) { is64 = 0; break; }
    g_tok64 = is64;
}

// ---------------------------------------------------------------------------
// Kernel 1: gather context embeddings -> fp16 X. grid (PM,PKC), 256 thr
// ---------------------------------------------------------------------------
__global__ void gather_ctx(const void* __restrict__ tokens, const float* __restrict__ emb) {
    int m = blockIdx.x, j = blockIdx.y;
    int t = m / PB, b = m - t * PB;
    int idx = t - PKC + j;
    long long tok = 0;
    if (idx >= 0) {
        size_t ofs = (size_t)idx * PB + b;
        tok = g_tok64 ? ((const long long*)tokens)[ofs]
                      : (long long)((const int*)tokens)[ofs];
    }
    if (tok < 0) tok = 0;
    if (tok >= PV) tok = PV - 1;
    float4 f = reinterpret_cast<const float4*>(emb + (size_t)tok * PD)[threadIdx.x];
    __half h[4] = { __float2half(f.x), __float2half(f.y),
                    __float2half(f.z), __float2half(f.w) };
    *reinterpret_cast<uint2*>(g_X + (size_t)m * PK1 + (size_t)j * PD
                              + (size_t)threadIdx.x * 4) = *reinterpret_cast<uint2*>(h);
}

// ---------------------------------------------------------------------------
// Kernel 2: W [K][N] fp32 -> k-pair-packed half2 [K/2][N]
// grid: (ceil(N/4/256), K/2), block 256
// ---------------------------------------------------------------------------
__global__ void pack_w(const float* __restrict__ W, uint32_t* __restrict__ Bp, int Nd) {
    int n4 = blockIdx.x * 256 + threadIdx.x;
    if (n4 >= (Nd >> 2)) return;
    size_t p = blockIdx.y;
    const float4 r0 = *reinterpret_cast<const float4*>(W + (2 * p    ) * (size_t)Nd + n4 * 4);
    const float4 r1 = *reinterpret_cast<const float4*>(W + (2 * p + 1) * (size_t)Nd + n4 * 4);
    uint4 o;
    o.x = pack2(r0.x, r1.x); o.y = pack2(r0.y, r1.y);
    o.z = pack2(r0.z, r1.z); o.w = pack2(r0.w, r1.w);
    *reinterpret_cast<uint4*>(Bp + p * (size_t)Nd + n4 * 4) = o;
}

// ---------------------------------------------------------------------------
// fp16 mma.sync GEMM: C = A(MxK,row,half) @ B(KxN via k-pair-packed) + bias
// CTA tile 128x256, BK=32, 4-stage cp.async, 8 warps (2M x 4N), warp 64x64.
// A smem [128][40] halves; B smem [16][264] uint32 (half2 k-pairs).
// EPI 0: silu -> half out. EPI 1: fp32 out.
// ---------------------------------------------------------------------------
#define BMT 128
#define BNT 256
#define BKT 32
#define NSTG 4
#define APADH 40                          // halves per A smem row
#define BPADW 264                         // uint32 per B smem row
#define A_BYTES (BMT*APADH*2)             // 10240
#define B_BYTES (16*BPADW*4)              // 16896
#define STG_BYTES (A_BYTES + B_BYTES)     // 27136
#define SMEM_BYTES (NSTG * STG_BYTES)     // 108544

__device__ __forceinline__ void issue_stage(
    uint32_t sm_base, int s, const __half* __restrict__ A, const uint32_t* __restrict__ Bp,
    int row0, int col0, int k0, int Kdim, int Ndim, int tid)
{
    uint32_t st = sm_base + (uint32_t)(s * STG_BYTES);
    // A: 128 rows x 32 halves = 512 16B chunks
    #pragma unroll
    for (int j = 0; j < 2; j++) {
        int i = tid + j * 256;
        int row = i >> 2, c = i & 3;
        cp_async16(st + (uint32_t)(row * (APADH * 2) + c * 16),
                   A + (size_t)(row0 + row) * Kdim + k0 + c * 8);
    }
    // B: 16 pair-rows x 256 uint32 = 1024 16B chunks
    uint32_t stb = st + A_BYTES;
    int p0 = k0 >> 1;
    #pragma unroll
    for (int j = 0; j < 4; j++) {
        int i = tid + j * 256;
        int row = i >> 6, c = i & 63;
        cp_async16(stb + (uint32_t)((row * BPADW + c * 4) * 4),
                   Bp + (size_t)(p0 + row) * Ndim + col0 + c * 4);
    }
}

template<int EPI>
__global__ __launch_bounds__(256, 1)
void mma_gemm(const __half* __restrict__ A, const uint32_t* __restrict__ Bp,
              const float* __restrict__ bias, void* __restrict__ Cv,
              int Ndim, int Kdim)
{
    extern __shared__ char smb[];
    const uint32_t sm_base = smem_u32(smb);

    const int tid = threadIdx.x;
    const int wid = tid >> 5, lane = tid & 31;
    const int wm = wid >> 2;             // 0..1 -> M offset wm*64
    const int wn = wid & 3;              // 0..3 -> N offset wn*64
    const int gq = lane >> 2;            // 0..7
    const int tg = lane & 3;             // 0..3

    const int row0 = blockIdx.x * BMT;
    const int col0 = blockIdx.y * BNT;
    const int NC = Kdim / BKT;

    float acc[4][8][4];
    #pragma unroll
    for (int mi = 0; mi < 4; mi++)
        #pragma unroll
        for (int ni = 0; ni < 8; ni++)
            #pragma unroll
            for (int q = 0; q < 4; q++) acc[mi][ni][q] = 0.0f;

    #pragma unroll
    for (int s = 0; s < NSTG - 1; s++) {
        issue_stage(sm_base, s, A, Bp, row0, col0, s * BKT, Kdim, Ndim, tid);
        cp_commit();
    }

    for (int c = 0; c < NC; c++) {
        int nc = c + NSTG - 1;
        if (nc < NC)
            issue_stage(sm_base, nc % NSTG, A, Bp, row0, col0, nc * BKT, Kdim, Ndim, tid);
        cp_commit();
        cp_wait<NSTG - 1>();
        __syncthreads();

        const __half* As = reinterpret_cast<const __half*>(smb + (c % NSTG) * STG_BYTES);
        const uint32_t* Bs = reinterpret_cast<const uint32_t*>(
            smb + (c % NSTG) * STG_BYTES + A_BYTES);

        #pragma unroll
        for (int ks = 0; ks < 2; ks++) {          // two k16 steps per chunk
            uint32_t af[4][4], bf[8][2];
            #pragma unroll
            for (int mi = 0; mi < 4; mi++) {
                int m0 = wm * 64 + mi * 16 + gq;
                const __half* r0p = As + (size_t)m0 * APADH + ks * 16 + tg * 2;
                const __half* r1p = r0p + 8 * APADH;
                af[mi][0] = *reinterpret_cast<const uint32_t*>(r0p);
                af[mi][1] = *reinterpret_cast<const uint32_t*>(r1p);
                af[mi][2] = *reinterpret_cast<const uint32_t*>(r0p + 8);
                af[mi][3] = *reinterpret_cast<const uint32_t*>(r1p + 8);
            }
            #pragma unroll
            for (int ni = 0; ni < 8; ni++) {
                int n0 = wn * 64 + ni * 8 + gq;
                bf[ni][0] = Bs[(ks * 8 + tg    ) * BPADW + n0];
                bf[ni][1] = Bs[(ks * 8 + tg + 4) * BPADW + n0];
            }
            #pragma unroll
            for (int mi = 0; mi < 4; mi++)
                #pragma unroll
                for (int ni = 0; ni < 8; ni++)
                    mma_f16(acc[mi][ni], af[mi], bf[ni]);
        }
        __syncthreads();
    }

    // Epilogue
    #pragma unroll
    for (int mi = 0; mi < 4; mi++) {
        const int r0 = row0 + wm * 64 + mi * 16 + gq;
        #pragma unroll
        for (int ni = 0; ni < 8; ni++) {
            const int cl = col0 + wn * 64 + ni * 8 + 2 * tg;
            float bb0 = bias[cl], bb1 = bias[cl + 1];
            float v0 = acc[mi][ni][0] + bb0, v1 = acc[mi][ni][1] + bb1;
            float v2 = acc[mi][ni][2] + bb0, v3 = acc[mi][ni][3] + bb1;
            if (EPI == 0) {
                __half* C = (__half*)Cv;
                v0 = v0 / (1.0f + expf(-v0));
                v1 = v1 / (1.0f + expf(-v1));
                v2 = v2 / (1.0f + expf(-v2));
                v3 = v3 / (1.0f + expf(-v3));
                __half2 p0 = __halves2half2(__float2half(v0), __float2half(v1));
                __half2 p1 = __halves2half2(__float2half(v2), __float2half(v3));
                *reinterpret_cast<__half2*>(C + (size_t)r0 * Ndim + cl) = p0;
                *reinterpret_cast<__half2*>(C + (size_t)(r0 + 8) * Ndim + cl) = p1;
            } else {
                float* C = (float*)Cv;
                *reinterpret_cast<float2*>(C + (size_t)r0 * Ndim + cl) = make_float2(v0, v1);
                *reinterpret_cast<float2*>(C + (size_t)(r0 + 8) * Ndim + cl) = make_float2(v2, v3);
            }
        }
    }
}

// ---------------------------------------------------------------------------
extern "C" void kernel_launch(void* const* d_in, const int* in_sizes, int n_in,
                              void* d_out, int out_size) {
    const void*  tokens = d_in[0];
    const float* emb = (const float*)d_in[1];
    const float* W1  = (const float*)d_in[2];
    const float* b1  = (const float*)d_in[3];
    const float* W2  = (const float*)d_in[4];
    const float* b2  = (const float*)d_in[5];
    float* out = (float*)d_out;

    __half *pX, *pH; uint32_t *pW1p, *pW2p;
    cudaGetSymbolAddress((void**)&pX, g_X);
    cudaGetSymbolAddress((void**)&pH, g_H);
    cudaGetSymbolAddress((void**)&pW1p, g_W1p);
    cudaGetSymbolAddress((void**)&pW2p, g_W2p);

    cudaFuncSetAttribute(mma_gemm<0>, cudaFuncAttributeMaxDynamicSharedMemorySize, SMEM_BYTES);
    cudaFuncSetAttribute(mma_gemm<1>, cudaFuncAttributeMaxDynamicSharedMemorySize, SMEM_BYTES);

    // 0) token dtype
    detect_tok_dtype<<<1, 1>>>((const unsigned int*)tokens);
    // 1) gather -> fp16 X
    gather_ctx<<<dim3(PM, PKC), 256>>>(tokens, emb);
    // 2) pack weights as k-pair half2
    pack_w<<<dim3((PD / 4 + 255) / 256, PK1 / 2), 256>>>(W1, pW1p, PD);
    pack_w<<<dim3((PV / 4 + 255) / 256, PD / 2), 256>>>(W2, pW2p, PV);
    // 3) H = silu(X @ W1 + b1)   M=4096,N=1024,K=3072
    mma_gemm<0><<<dim3(PM / BMT, PD / BNT), 256, SMEM_BYTES>>>(pX, pW1p, b1, pH, PD, PK1);
    // 4) out = H @ W2 + b2       M=4096,N=32000,K=1024
    mma_gemm<1><<<dim3(PM / BMT, PV / BNT), 256, SMEM_BYTES>>>(pH, pW2p, b2, out, PV, PD);
}